// round 12
// baseline (speedup 1.0000x reference)
#include <cuda_runtime.h>
#include <cuda_bf16.h>
#include <cstdint>

// Problem constants
#define B_    4
#define N_    512
#define T_    10
#define F_    516      // N + 4
#define HID   128
#define MSGD  32
#define UPDH  128
#define OUTD  4

// kB tiling (mma.sync version)
#define NI      128                 // i per CTA (MMA N total)
#define JSPLIT  16                  // j split across CTAs
#define JCHUNK  (N_ / JSPLIT)       // 32 j per CTA
#define NSLICE  JSPLIT              // 16 partial slices
#define ROWB    80                  // padded smem row bytes (32 bf16 = 64B + 16 pad)

// Scratch (static device arrays: no allocations allowed)
__device__ float g_C[B_ * N_ * HID];                 // C[b,j,hid], mb1 folded in
__device__ float g_part[NSLICE * B_ * N_ * HID];     // per-js partial H_sum

// ===========================================================================
// Helpers: baseline-ISA tensor ops (sm_80+ -> compile for compute_100)
// ===========================================================================
__device__ __forceinline__ uint32_t smem_u32(const void* p) {
    uint32_t a;
    asm("{ .reg .u64 t; cvta.to.shared.u64 t, %1; cvt.u32.u64 %0, t; }"
        : "=r"(a) : "l"(p));
    return a;
}
__device__ __forceinline__ void ldm_x4(uint32_t& r0, uint32_t& r1,
                                       uint32_t& r2, uint32_t& r3, uint32_t addr) {
    asm volatile("ldmatrix.sync.aligned.m8n8.x4.shared.b16 {%0,%1,%2,%3}, [%4];"
                 : "=r"(r0), "=r"(r1), "=r"(r2), "=r"(r3) : "r"(addr));
}
__device__ __forceinline__ void mma_16816(float& d0, float& d1, float& d2, float& d3,
                                          uint32_t a0, uint32_t a1, uint32_t a2, uint32_t a3,
                                          uint32_t b0, uint32_t b1) {
    asm volatile(
        "mma.sync.aligned.m16n8k16.row.col.f32.bf16.bf16.f32 "
        "{%0,%1,%2,%3},{%4,%5,%6,%7},{%8,%9},{%0,%1,%2,%3};"
        : "+f"(d0), "+f"(d1), "+f"(d2), "+f"(d3)
        : "r"(a0), "r"(a1), "r"(a2), "r"(a3), "r"(b0), "r"(b1));
}
// pack {low=lo_elem, high=hi_elem} into one bf16x2 register
__device__ __forceinline__ uint32_t pack_bf16x2(float lo_elem, float hi_elem) {
    uint32_t r;
    asm("cvt.rn.bf16x2.f32 %0, %1, %2;" : "=r"(r) : "f"(hi_elem), "f"(lo_elem));
    return r;
}

// Split v into bf16 hi + residual lo
__device__ __forceinline__ void split_hilo(const float* v, float* hif, float* lof) {
#pragma unroll
    for (int q = 0; q < 10; ++q) {
        __nv_bfloat16 h = __float2bfloat16(v[q]);
        hif[q] = __bfloat162float(h);
        lof[q] = v[q] - hif[q];
    }
}
// W row layout: [hi(k0-9) | hi(k10-19) | lo(k20-29) | 0,0]
__device__ __forceinline__ void build_row_w(const float* v, uint32_t* u) {
    float hif[10], lof[10];
    split_hilo(v, hif, lof);
#pragma unroll
    for (int p = 0; p < 5; ++p) {
        u[p]      = pack_bf16x2(hif[2 * p], hif[2 * p + 1]);
        u[5 + p]  = u[p];
        u[10 + p] = pack_bf16x2(lof[2 * p], lof[2 * p + 1]);
    }
    u[15] = 0u;
}
// E row layout: [hi(k0-9) | lo(k10-19) | hi(k20-29) | 0,0]
// => dot(W,E) = w_hi*e_hi + w_hi*e_lo + w_lo*e_hi  (3-term compensated)
__device__ __forceinline__ void build_row_e(const float* v, uint32_t* u) {
    float hif[10], lof[10];
    split_hilo(v, hif, lof);
#pragma unroll
    for (int p = 0; p < 5; ++p) {
        u[p]      = pack_bf16x2(hif[2 * p], hif[2 * p + 1]);
        u[5 + p]  = pack_bf16x2(lof[2 * p], lof[2 * p + 1]);
        u[10 + p] = u[p];
    }
    u[15] = 0u;
}

// ---------------------------------------------------------------------------
// Kernel A: C[b,j,hid] = mb1[hid] + sum_{t,k<4} x[b,j,t,k] * mW1[5t+k, hid]
// ---------------------------------------------------------------------------
#define ABJ 2
__global__ __launch_bounds__(128) void kA(const float* __restrict__ x,
                                          const float* __restrict__ mW1,
                                          const float* __restrict__ mb1) {
    const int hid = threadIdx.x;
    float w[40];
#pragma unroll
    for (int r = 0; r < 40; ++r)
        w[r] = mW1[(5 * (r >> 2) + (r & 3)) * HID + hid];
    const float bias = mb1[hid];

    __shared__ float sb[ABJ][40];
    const int bj0 = blockIdx.x * ABJ;
    if (hid < ABJ * 40) {
        const int nn = hid / 40, r = hid % 40;
        sb[nn][r] = x[((long)(bj0 + nn) * T_ + (r >> 2)) * F_ + (r & 3)];
    }
    __syncthreads();

    float acc[ABJ];
#pragma unroll
    for (int nn = 0; nn < ABJ; ++nn) acc[nn] = bias;
#pragma unroll
    for (int r = 0; r < 40; ++r) {
        const float wr = w[r];
#pragma unroll
        for (int nn = 0; nn < ABJ; ++nn) acc[nn] = fmaf(sb[nn][r], wr, acc[nn]);
    }
#pragma unroll
    for (int nn = 0; nn < ABJ; ++nn)
        g_C[(long)(bj0 + nn) * HID + hid] = acc[nn];
}

// ---------------------------------------------------------------------------
// Kernel B (mma.sync): CTA = (i-block of 128, b, j-16th). 256 thr / 8 warps.
//   P[h,i] = W'[h,32k] @ E'[32k,i]   (3-term bf16 split, k30/31 zero)
//   D init = C[b,j,h] (rows of D frag depend only on lane/4 -> free C add)
//   acc[h,i] += relu(D)
// Warp w owns h-tile [16w,16w+16) (one m16), all 128 i (16 n8 tiles).
// A (weights) stationary in 8 regs; E double-buffered smem, 1 sync per j.
// ---------------------------------------------------------------------------
__global__ __launch_bounds__(256, 2) void kB(const float* __restrict__ x,
                                             const float* __restrict__ mW1) {
    __shared__ __align__(16) unsigned char s_all[31744];
    // carve: W 0..10240 | E0 10240..20480 | E1 20480..30720 | C0 | C1
    unsigned char* s_w = s_all;
    unsigned char* s_e[2] = {s_all + 10240, s_all + 20480};
    float* s_c[2] = {reinterpret_cast<float*>(s_all + 30720),
                     reinterpret_cast<float*>(s_all + 31232)};

    const int tid  = threadIdx.x;
    const int lane = tid & 31, wid = tid >> 5;
    const int i0   = blockIdx.x * NI;        // 0,128,256,384
    const int b    = blockIdx.y;             // 0..3
    const int js   = blockIdx.z;             // 0..15
    const int jbase = js * JCHUNK;

    const int row  = tid >> 1;               // staged i-row (0..127)
    const int half = tid & 1;                // which 16-k half this thread stores
    const long estr = (long)T_ * F_;

    // ---- stationary weight tile W'[128h][32k] ----
    if (tid < HID) {
        float wv[10];
#pragma unroll
        for (int t = 0; t < T_; ++t) wv[t] = mW1[(5 * t + 4) * HID + tid];
        uint32_t u[16];
        build_row_w(wv, u);
        uint4* dst = reinterpret_cast<uint4*>(s_w + tid * ROWB);
        dst[0] = make_uint4(u[0], u[1], u[2], u[3]);
        dst[1] = make_uint4(u[4], u[5], u[6], u[7]);
        dst[2] = make_uint4(u[8], u[9], u[10], u[11]);
        dst[3] = make_uint4(u[12], u[13], u[14], u[15]);
    }

    // ---- stage j0 (E + C) ----
    const float* eg = x + ((long)(b * N_ + jbase) * T_) * F_ + 4 + i0 + row;
    const float* cg = g_C + (long)(b * N_ + jbase) * HID;
    {
        float v[10];
#pragma unroll
        for (int t = 0; t < T_; ++t) v[t] = eg[t * F_];
        uint32_t u[16];
        build_row_e(v, u);
        uint4* dst = reinterpret_cast<uint4*>(s_e[0] + row * ROWB + half * 32);
        dst[0] = make_uint4(u[half * 8 + 0], u[half * 8 + 1], u[half * 8 + 2], u[half * 8 + 3]);
        dst[1] = make_uint4(u[half * 8 + 4], u[half * 8 + 5], u[half * 8 + 6], u[half * 8 + 7]);
        if (half == 0) s_c[0][row] = cg[row];
    }
    __syncthreads();

    // ---- load stationary A fragments (2 k-steps) ----
    uint32_t a[8];
    {
        const uint32_t wbase = smem_u32(s_w);
        const uint32_t aoff = (uint32_t)((wid * 16 + ((lane >> 3) & 1) * 8 + (lane & 7)) * ROWB
                                         + (lane >> 4) * 16);
        ldm_x4(a[0], a[1], a[2], a[3], wbase + aoff);
        ldm_x4(a[4], a[5], a[6], a[7], wbase + aoff + 32);
    }

    const uint32_t eoff = (uint32_t)((lane & 7) * ROWB + (lane >> 3) * 16);
    const uint32_t ebase[2] = {smem_u32(s_e[0]) + eoff, smem_u32(s_e[1]) + eoff};

    float acc[64];
#pragma unroll
    for (int q = 0; q < 64; ++q) acc[q] = 0.f;

#pragma unroll 1
    for (int jj = 0; jj < JCHUNK; ++jj) {
        const int buf = jj & 1;

        // prefetch next j's e (+C) into registers
        float vP[10]; float cP = 0.f;
        if (jj + 1 < JCHUNK) {
            const float* ep = eg + (long)(jj + 1) * estr;
#pragma unroll
            for (int t = 0; t < T_; ++t) vP[t] = ep[t * F_];
            if (half == 0) cP = cg[(long)(jj + 1) * HID + row];
        }

        // ---- compute j from buf ----
        {
            const float cA = s_c[buf][wid * 16 + (lane >> 2)];
            const float cB = s_c[buf][wid * 16 + (lane >> 2) + 8];
            const uint32_t eb = ebase[buf];
#pragma unroll
            for (int n = 0; n < 16; ++n) {
                uint32_t b0, b1, b2, b3;
                ldm_x4(b0, b1, b2, b3, eb + n * (8 * ROWB));
                float d0 = cA, d1 = cA, d2 = cB, d3 = cB;
                mma_16816(d0, d1, d2, d3, a[0], a[1], a[2], a[3], b0, b1);
                mma_16816(d0, d1, d2, d3, a[4], a[5], a[6], a[7], b2, b3);
                acc[n * 4 + 0] += fmaxf(d0, 0.f);
                acc[n * 4 + 1] += fmaxf(d1, 0.f);
                acc[n * 4 + 2] += fmaxf(d2, 0.f);
                acc[n * 4 + 3] += fmaxf(d3, 0.f);
            }
        }

        // ---- stage next j into other buffer ----
        if (jj + 1 < JCHUNK) {
            uint32_t u[16];
            build_row_e(vP, u);
            uint4* dst = reinterpret_cast<uint4*>(s_e[buf ^ 1] + row * ROWB + half * 32);
            dst[0] = make_uint4(u[half * 8 + 0], u[half * 8 + 1], u[half * 8 + 2], u[half * 8 + 3]);
            dst[1] = make_uint4(u[half * 8 + 4], u[half * 8 + 5], u[half * 8 + 6], u[half * 8 + 7]);
            if (half == 0) s_c[buf ^ 1][row] = cP;
        }
        __syncthreads();
    }

    // ---- epilogue: per-warp smem transpose -> coalesced g_part stores ----
    float* s_tr = reinterpret_cast<float*>(s_all + 10240);   // 128 i x 16 h = 8 KB
    for (int r = 0; r < 8; ++r) {
        if (wid == r) {
#pragma unroll
            for (int n = 0; n < 16; ++n) {
#pragma unroll
                for (int p = 0; p < 4; ++p) {
                    const int iL = n * 8 + (lane & 3) * 2 + (p & 1);
                    const int hL = (lane >> 2) + ((p >> 1) << 3);
                    s_tr[iL * 16 + hL] = acc[n * 4 + p];
                }
            }
        }
        __syncthreads();
        {
            const int iL = tid >> 1, seg = tid & 1;
            const float4* src = reinterpret_cast<const float4*>(s_tr + iL * 16 + seg * 8);
            float* dst = g_part + ((long)(js * B_ + b) * N_ + i0 + iL) * HID + r * 16 + seg * 8;
            reinterpret_cast<float4*>(dst)[0] = src[0];
            reinterpret_cast<float4*>(dst)[1] = src[1];
        }
        __syncthreads();
    }
}

// ---------------------------------------------------------------------------
// Kernel C: per node — reduce 16 partial slices, apply mW2 (+ N*mb2),
// concat node_feat, 36 -> 128 (relu) -> 4 MLP. Block = 16 nodes, weights smem.
// ---------------------------------------------------------------------------
#define NPB 16
__global__ __launch_bounds__(128) void kC(const float* __restrict__ x,
                                          const float* __restrict__ mW2,
                                          const float* __restrict__ mb2,
                                          const float* __restrict__ iW1,
                                          const float* __restrict__ ib1,
                                          const float* __restrict__ iW2,
                                          const float* __restrict__ ib2,
                                          float* __restrict__ out) {
    const int tid = threadIdx.x;

    __shared__ float s_mW2[HID * MSGD];
    __shared__ float s_iW1[(MSGD + 4) * UPDH];
    __shared__ float s_iW2[UPDH * OUTD];
    __shared__ float s_mb2[MSGD], s_ib1[UPDH], s_ib2[OUTD];
    __shared__ float s_h[HID];
    __shared__ float s_red[4][MSGD];
    __shared__ float s_mi[MSGD + 4];
    __shared__ float s_h2[UPDH];
    __shared__ float s_nf[NPB][4];

    for (int i = tid; i < HID * MSGD; i += 128)        s_mW2[i] = mW2[i];
    for (int i = tid; i < (MSGD + 4) * UPDH; i += 128) s_iW1[i] = iW1[i];
    for (int i = tid; i < UPDH * OUTD; i += 128)       s_iW2[i] = iW2[i];
    if (tid < MSGD) s_mb2[tid] = mb2[tid];
    s_ib1[tid] = ib1[tid];
    if (tid < OUTD) s_ib2[tid] = ib2[tid];
    if (tid < NPB * 4) {
        const int nn = tid >> 2, k = tid & 3;
        s_nf[nn][k] = x[((long)(blockIdx.x * NPB + nn) * T_ + (T_ - 1)) * F_ + k];
    }
    __syncthreads();

    for (int nn = 0; nn < NPB; ++nn) {
        const long node = (long)blockIdx.x * NPB + nn;

        float h = 0.f;
#pragma unroll
        for (int p = 0; p < NSLICE; ++p)
            h += g_part[(long)p * (B_ * N_ * HID) + node * HID + tid];
        s_h[tid] = h;
        __syncthreads();

        {   // mW2 GEMV split 4 ways over k
            const int m = tid & 31, seg = tid >> 5;
            float a = 0.f;
#pragma unroll
            for (int k2 = 0; k2 < 32; ++k2) {
                const int k = seg * 32 + k2;
                a = fmaf(s_h[k], s_mW2[k * MSGD + m], a);
            }
            s_red[seg][m] = a;
        }
        __syncthreads();
        if (tid < MSGD)
            s_mi[tid] = s_red[0][tid] + s_red[1][tid] + s_red[2][tid] + s_red[3][tid]
                      + (float)N_ * s_mb2[tid];
        if (tid < 4) s_mi[MSGD + tid] = s_nf[nn][tid];
        __syncthreads();

        {   // 36 -> 128 relu
            float a = s_ib1[tid];
#pragma unroll
            for (int k = 0; k < MSGD + 4; ++k)
                a = fmaf(s_mi[k], s_iW1[k * UPDH + tid], a);
            s_h2[tid] = fmaxf(a, 0.f);
        }
        __syncthreads();

        {   // 128 -> 4: warp o computes output o, shuffle-reduce
            const int o = tid >> 5, lane = tid & 31;
            float a = 0.f;
#pragma unroll
            for (int kk = 0; kk < 4; ++kk) {
                const int k = lane + kk * 32;
                a = fmaf(s_h2[k], s_iW2[k * OUTD + o], a);
            }
#pragma unroll
            for (int off = 16; off; off >>= 1) a += __shfl_xor_sync(~0u, a, off);
            if (lane == 0) out[node * OUTD + o] = a + s_ib2[o];
        }
        __syncthreads();
    }
}

// ---------------------------------------------------------------------------
extern "C" void kernel_launch(void* const* d_in, const int* in_sizes, int n_in,
                              void* d_out, int out_size) {
    const float* x   = (const float*)d_in[0];
    const float* mW1 = (const float*)d_in[1];
    const float* mb1 = (const float*)d_in[2];
    const float* mW2 = (const float*)d_in[3];
    const float* mb2 = (const float*)d_in[4];
    const float* iW1 = (const float*)d_in[5];
    const float* ib1 = (const float*)d_in[6];
    const float* iW2 = (const float*)d_in[7];
    const float* ib2 = (const float*)d_in[8];
    float* out = (float*)d_out;

    kA<<<B_ * N_ / ABJ, HID>>>(x, mW1, mb1);          // 1024 blocks

    dim3 gB(N_ / NI, B_, JSPLIT);                     // (4, 4, 16) = 256 CTAs
    kB<<<gB, 256>>>(x, mW1);

    kC<<<B_ * N_ / NPB, HID>>>(x, mW2, mb2, iW1, ib1, iW2, ib2, out);
}

// round 13
// speedup vs baseline: 1.4201x; 1.4201x over previous
#include <cuda_runtime.h>
#include <cuda_bf16.h>
#include <cstdint>

// Problem constants
#define B_    4
#define N_    512
#define T_    10
#define F_    516      // N + 4
#define HID   128
#define MSGD  32
#define UPDH  128
#define OUTD  4

// kB tiling (mma.sync version, K=16 hi-only)
#define NI      128                 // i per CTA (MMA N total)
#define JSPLIT  16                  // j split across CTAs
#define JCHUNK  (N_ / JSPLIT)       // 32 j per CTA
#define NSLICE  JSPLIT              // 16 partial slices
#define ROWB    48                  // padded smem row bytes (16 bf16 = 32B + 16 pad)

// Scratch (static device arrays: no allocations allowed)
__device__ float g_C[B_ * N_ * HID];                 // C[b,j,hid], mb1 folded in
__device__ float g_part[NSLICE * B_ * N_ * HID];     // per-js partial H_sum

// ===========================================================================
// Helpers: baseline-ISA tensor ops (sm_80+ -> compile for compute_100)
// ===========================================================================
__device__ __forceinline__ uint32_t smem_u32(const void* p) {
    uint32_t a;
    asm("{ .reg .u64 t; cvta.to.shared.u64 t, %1; cvt.u32.u64 %0, t; }"
        : "=r"(a) : "l"(p));
    return a;
}
__device__ __forceinline__ void ldm_x4(uint32_t& r0, uint32_t& r1,
                                       uint32_t& r2, uint32_t& r3, uint32_t addr) {
    asm volatile("ldmatrix.sync.aligned.m8n8.x4.shared.b16 {%0,%1,%2,%3}, [%4];"
                 : "=r"(r0), "=r"(r1), "=r"(r2), "=r"(r3) : "r"(addr));
}
__device__ __forceinline__ void mma_16816(float& d0, float& d1, float& d2, float& d3,
                                          uint32_t a0, uint32_t a1, uint32_t a2, uint32_t a3,
                                          uint32_t b0, uint32_t b1) {
    asm volatile(
        "mma.sync.aligned.m16n8k16.row.col.f32.bf16.bf16.f32 "
        "{%0,%1,%2,%3},{%4,%5,%6,%7},{%8,%9},{%0,%1,%2,%3};"
        : "+f"(d0), "+f"(d1), "+f"(d2), "+f"(d3)
        : "r"(a0), "r"(a1), "r"(a2), "r"(a3), "r"(b0), "r"(b1));
}
// pack two floats to bf16x2 {low, high}
__device__ __forceinline__ uint32_t pack_bf16x2(float lo_elem, float hi_elem) {
    uint32_t r;
    asm("cvt.rn.bf16x2.f32 %0, %1, %2;" : "=r"(r) : "f"(hi_elem), "f"(lo_elem));
    return r;
}

// ---------------------------------------------------------------------------
// Kernel A: C[b,j,hid] = mb1[hid] + sum_{t,k<4} x[b,j,t,k] * mW1[5t+k, hid]
// (fp32-exact; C enters the MMA as the D initializer, so the dominant base
//  term never suffers bf16 rounding)
// ---------------------------------------------------------------------------
#define ABJ 2
__global__ __launch_bounds__(128) void kA(const float* __restrict__ x,
                                          const float* __restrict__ mW1,
                                          const float* __restrict__ mb1) {
    const int hid = threadIdx.x;
    float w[40];
#pragma unroll
    for (int r = 0; r < 40; ++r)
        w[r] = mW1[(5 * (r >> 2) + (r & 3)) * HID + hid];
    const float bias = mb1[hid];

    __shared__ float sb[ABJ][40];
    const int bj0 = blockIdx.x * ABJ;
    if (hid < ABJ * 40) {
        const int nn = hid / 40, r = hid % 40;
        sb[nn][r] = x[((long)(bj0 + nn) * T_ + (r >> 2)) * F_ + (r & 3)];
    }
    __syncthreads();

    float acc[ABJ];
#pragma unroll
    for (int nn = 0; nn < ABJ; ++nn) acc[nn] = bias;
#pragma unroll
    for (int r = 0; r < 40; ++r) {
        const float wr = w[r];
#pragma unroll
        for (int nn = 0; nn < ABJ; ++nn) acc[nn] = fmaf(sb[nn][r], wr, acc[nn]);
    }
#pragma unroll
    for (int nn = 0; nn < ABJ; ++nn)
        g_C[(long)(bj0 + nn) * HID + hid] = acc[nn];
}

// ---------------------------------------------------------------------------
// Kernel B (mma.sync, K=16): CTA = (i-block of 128, b, j-16th). 256 thr/8 w.
//   P[h,i] = W_hi[h,16k] @ E_hi[16k,i]  (k0-9 = t, k10-15 = 0)
//   D init = C[b,j,h] fp32  ->  acc[h,i] += relu(D)
// Warp w owns h-tile [16w,16w+16); 16 n8 i-tiles; ONE mma per tile.
// Paired B-ldsm: one ldmatrix.x4 feeds two n-tiles.
// ---------------------------------------------------------------------------
__global__ __launch_bounds__(256, 2) void kB(const float* __restrict__ x,
                                             const float* __restrict__ mW1) {
    __shared__ __align__(16) unsigned char s_all[19456];
    // carve: W 0..6144 | E0 6144..12288 | E1 12288..18432 | C0 | C1
    unsigned char* s_w = s_all;
    unsigned char* s_e[2] = {s_all + 6144, s_all + 12288};
    float* s_c[2] = {reinterpret_cast<float*>(s_all + 18432),
                     reinterpret_cast<float*>(s_all + 18944)};

    const int tid  = threadIdx.x;
    const int lane = tid & 31, wid = tid >> 5;
    const int i0   = blockIdx.x * NI;        // 0,128,256,384
    const int b    = blockIdx.y;             // 0..3
    const int js   = blockIdx.z;             // 0..15
    const int jbase = js * JCHUNK;

    const int row  = tid >> 1;               // staged i-row (0..127)
    const int half = tid & 1;                // which 8-k half this thread stores
    const long estr = (long)T_ * F_;

    // ---- stationary weight tile W_hi[128h][16k] ----
    if (tid < HID) {
        float wv[10];
#pragma unroll
        for (int t = 0; t < T_; ++t) wv[t] = mW1[(5 * t + 4) * HID + tid];
        uint4* dst = reinterpret_cast<uint4*>(s_w + tid * ROWB);
        dst[0] = make_uint4(pack_bf16x2(wv[0], wv[1]), pack_bf16x2(wv[2], wv[3]),
                            pack_bf16x2(wv[4], wv[5]), pack_bf16x2(wv[6], wv[7]));
        dst[1] = make_uint4(pack_bf16x2(wv[8], wv[9]), 0u, 0u, 0u);
    }

    // ---- stage j0 (E + C) ----
    const float* eg = x + ((long)(b * N_ + jbase) * T_) * F_ + 4 + i0 + row;
    const float* cg = g_C + (long)(b * N_ + jbase) * HID;
    {
        float v[10];
#pragma unroll
        for (int t = 0; t < T_; ++t) v[t] = eg[t * F_];
        uint4* dst = reinterpret_cast<uint4*>(s_e[0] + row * ROWB + half * 16);
        if (half == 0) {
            dst[0] = make_uint4(pack_bf16x2(v[0], v[1]), pack_bf16x2(v[2], v[3]),
                                pack_bf16x2(v[4], v[5]), pack_bf16x2(v[6], v[7]));
            s_c[0][row] = cg[row];
        } else {
            dst[0] = make_uint4(pack_bf16x2(v[8], v[9]), 0u, 0u, 0u);
        }
    }
    __syncthreads();

    // ---- load stationary A fragment (m16 x k16) ----
    uint32_t a0, a1, a2, a3;
    {
        const uint32_t wbase = smem_u32(s_w);
        const uint32_t aoff = (uint32_t)((wid * 16 + ((lane >> 3) & 1) * 8 + (lane & 7)) * ROWB
                                         + (lane >> 4) * 16);
        ldm_x4(a0, a1, a2, a3, wbase + aoff);
    }

    // paired-B ldsm lane mapping: tiles {n: k0-7, n: k8-15, n+1: k0-7, n+1: k8-15}
    const uint32_t eoff = (uint32_t)(((lane >> 4) * 8 + (lane & 7)) * ROWB
                                     + ((lane >> 3) & 1) * 16);
    const uint32_t ebase[2] = {smem_u32(s_e[0]) + eoff, smem_u32(s_e[1]) + eoff};

    float acc[64];
#pragma unroll
    for (int q = 0; q < 64; ++q) acc[q] = 0.f;

#pragma unroll 1
    for (int jj = 0; jj < JCHUNK; ++jj) {
        const int buf = jj & 1;

        // prefetch next j's e (+C) into registers
        float vP[10]; float cP = 0.f;
        if (jj + 1 < JCHUNK) {
            const float* ep = eg + (long)(jj + 1) * estr;
#pragma unroll
            for (int t = 0; t < T_; ++t) vP[t] = ep[t * F_];
            if (half == 0) cP = cg[(long)(jj + 1) * HID + row];
        }

        // ---- compute j from buf ----
        {
            const float cA = s_c[buf][wid * 16 + (lane >> 2)];
            const float cB = s_c[buf][wid * 16 + (lane >> 2) + 8];
            const uint32_t eb = ebase[buf];
#pragma unroll
            for (int n = 0; n < 16; n += 2) {
                uint32_t b0, b1, b2, b3;
                ldm_x4(b0, b1, b2, b3, eb + n * (8 * ROWB));
                float d0 = cA, d1 = cA, d2 = cB, d3 = cB;
                mma_16816(d0, d1, d2, d3, a0, a1, a2, a3, b0, b1);
                float e0 = cA, e1 = cA, e2 = cB, e3 = cB;
                mma_16816(e0, e1, e2, e3, a0, a1, a2, a3, b2, b3);
                acc[n * 4 + 0] += fmaxf(d0, 0.f);
                acc[n * 4 + 1] += fmaxf(d1, 0.f);
                acc[n * 4 + 2] += fmaxf(d2, 0.f);
                acc[n * 4 + 3] += fmaxf(d3, 0.f);
                acc[n * 4 + 4] += fmaxf(e0, 0.f);
                acc[n * 4 + 5] += fmaxf(e1, 0.f);
                acc[n * 4 + 6] += fmaxf(e2, 0.f);
                acc[n * 4 + 7] += fmaxf(e3, 0.f);
            }
        }

        // ---- stage next j into other buffer ----
        if (jj + 1 < JCHUNK) {
            uint4* dst = reinterpret_cast<uint4*>(s_e[buf ^ 1] + row * ROWB + half * 16);
            if (half == 0) {
                dst[0] = make_uint4(pack_bf16x2(vP[0], vP[1]), pack_bf16x2(vP[2], vP[3]),
                                    pack_bf16x2(vP[4], vP[5]), pack_bf16x2(vP[6], vP[7]));
                s_c[buf ^ 1][row] = cP;
            } else {
                dst[0] = make_uint4(pack_bf16x2(vP[8], vP[9]), 0u, 0u, 0u);
            }
        }
        __syncthreads();
    }

    // ---- epilogue: per-warp smem transpose -> coalesced g_part stores ----
    float* s_tr = reinterpret_cast<float*>(s_all + 6144);   // 128 i x 16 h = 8 KB
    for (int r = 0; r < 8; ++r) {
        if (wid == r) {
#pragma unroll
            for (int n = 0; n < 16; ++n) {
#pragma unroll
                for (int p = 0; p < 4; ++p) {
                    const int iL = n * 8 + (lane & 3) * 2 + (p & 1);
                    const int hL = (lane >> 2) + ((p >> 1) << 3);
                    s_tr[iL * 16 + hL] = acc[n * 4 + p];
                }
            }
        }
        __syncthreads();
        {
            const int iL = tid >> 1, seg = tid & 1;
            const float4* src = reinterpret_cast<const float4*>(s_tr + iL * 16 + seg * 8);
            float* dst = g_part + ((long)(js * B_ + b) * N_ + i0 + iL) * HID + r * 16 + seg * 8;
            reinterpret_cast<float4*>(dst)[0] = src[0];
            reinterpret_cast<float4*>(dst)[1] = src[1];
        }
        __syncthreads();
    }
}

// ---------------------------------------------------------------------------
// Kernel C: per node — reduce 16 partial slices, apply mW2 (+ N*mb2),
// concat node_feat, 36 -> 128 (relu) -> 4 MLP. Block = 16 nodes, weights smem.
// ---------------------------------------------------------------------------
#define NPB 16
__global__ __launch_bounds__(128) void kC(const float* __restrict__ x,
                                          const float* __restrict__ mW2,
                                          const float* __restrict__ mb2,
                                          const float* __restrict__ iW1,
                                          const float* __restrict__ ib1,
                                          const float* __restrict__ iW2,
                                          const float* __restrict__ ib2,
                                          float* __restrict__ out) {
    const int tid = threadIdx.x;

    __shared__ float s_mW2[HID * MSGD];
    __shared__ float s_iW1[(MSGD + 4) * UPDH];
    __shared__ float s_iW2[UPDH * OUTD];
    __shared__ float s_mb2[MSGD], s_ib1[UPDH], s_ib2[OUTD];
    __shared__ float s_h[HID];
    __shared__ float s_red[4][MSGD];
    __shared__ float s_mi[MSGD + 4];
    __shared__ float s_h2[UPDH];
    __shared__ float s_nf[NPB][4];

    for (int i = tid; i < HID * MSGD; i += 128)        s_mW2[i] = mW2[i];
    for (int i = tid; i < (MSGD + 4) * UPDH; i += 128) s_iW1[i] = iW1[i];
    for (int i = tid; i < UPDH * OUTD; i += 128)       s_iW2[i] = iW2[i];
    if (tid < MSGD) s_mb2[tid] = mb2[tid];
    s_ib1[tid] = ib1[tid];
    if (tid < OUTD) s_ib2[tid] = ib2[tid];
    if (tid < NPB * 4) {
        const int nn = tid >> 2, k = tid & 3;
        s_nf[nn][k] = x[((long)(blockIdx.x * NPB + nn) * T_ + (T_ - 1)) * F_ + k];
    }
    __syncthreads();

    for (int nn = 0; nn < NPB; ++nn) {
        const long node = (long)blockIdx.x * NPB + nn;

        float h = 0.f;
#pragma unroll
        for (int p = 0; p < NSLICE; ++p)
            h += g_part[(long)p * (B_ * N_ * HID) + node * HID + tid];
        s_h[tid] = h;
        __syncthreads();

        {   // mW2 GEMV split 4 ways over k
            const int m = tid & 31, seg = tid >> 5;
            float a = 0.f;
#pragma unroll
            for (int k2 = 0; k2 < 32; ++k2) {
                const int k = seg * 32 + k2;
                a = fmaf(s_h[k], s_mW2[k * MSGD + m], a);
            }
            s_red[seg][m] = a;
        }
        __syncthreads();
        if (tid < MSGD)
            s_mi[tid] = s_red[0][tid] + s_red[1][tid] + s_red[2][tid] + s_red[3][tid]
                      + (float)N_ * s_mb2[tid];
        if (tid < 4) s_mi[MSGD + tid] = s_nf[nn][tid];
        __syncthreads();

        {   // 36 -> 128 relu
            float a = s_ib1[tid];
#pragma unroll
            for (int k = 0; k < MSGD + 4; ++k)
                a = fmaf(s_mi[k], s_iW1[k * UPDH + tid], a);
            s_h2[tid] = fmaxf(a, 0.f);
        }
        __syncthreads();

        {   // 128 -> 4: warp o computes output o, shuffle-reduce
            const int o = tid >> 5, lane = tid & 31;
            float a = 0.f;
#pragma unroll
            for (int kk = 0; kk < 4; ++kk) {
                const int k = lane + kk * 32;
                a = fmaf(s_h2[k], s_iW2[k * OUTD + o], a);
            }
#pragma unroll
            for (int off = 16; off; off >>= 1) a += __shfl_xor_sync(~0u, a, off);
            if (lane == 0) out[node * OUTD + o] = a + s_ib2[o];
        }
        __syncthreads();
    }
}

// ---------------------------------------------------------------------------
extern "C" void kernel_launch(void* const* d_in, const int* in_sizes, int n_in,
                              void* d_out, int out_size) {
    const float* x   = (const float*)d_in[0];
    const float* mW1 = (const float*)d_in[1];
    const float* mb1 = (const float*)d_in[2];
    const float* mW2 = (const float*)d_in[3];
    const float* mb2 = (const float*)d_in[4];
    const float* iW1 = (const float*)d_in[5];
    const float* ib1 = (const float*)d_in[6];
    const float* iW2 = (const float*)d_in[7];
    const float* ib2 = (const float*)d_in[8];
    float* out = (float*)d_out;

    kA<<<B_ * N_ / ABJ, HID>>>(x, mW1, mb1);          // 1024 blocks

    dim3 gB(N_ / NI, B_, JSPLIT);                     // (4, 4, 16) = 256 CTAs
    kB<<<gB, 256>>>(x, mW1);

    kC<<<B_ * N_ / NPB, HID>>>(x, mW2, mb2, iW1, ib1, iW2, ib2, out);
}

// round 15
// speedup vs baseline: 1.5184x; 1.0692x over previous
#include <cuda_runtime.h>
#include <cuda_bf16.h>
#include <cstdint>

// Problem constants
#define B_    4
#define N_    512
#define T_    10
#define F_    516      // N + 4
#define HID   128
#define MSGD  32
#define UPDH  128
#define OUTD  4

// kB tiling (mma.sync, K=16 hi-only)
#define NI      128                 // i per CTA (MMA N total)
#define JSPLIT  16                  // j split across CTAs
#define JCHUNK  (N_ / JSPLIT)       // 32 j per CTA
#define NSLICE  JSPLIT              // 16 partial slices
#define ROWB    48                  // padded smem row bytes (16 bf16 = 32B + 16 pad)

// Scratch (static device arrays: no allocations allowed)
__device__ float g_part[NSLICE * B_ * N_ * HID];     // per-js partial H_sum

// ===========================================================================
// Helpers
// ===========================================================================
__device__ __forceinline__ uint32_t smem_u32(const void* p) {
    uint32_t a;
    asm("{ .reg .u64 t; cvta.to.shared.u64 t, %1; cvt.u32.u64 %0, t; }"
        : "=r"(a) : "l"(p));
    return a;
}
__device__ __forceinline__ void ldm_x4(uint32_t& r0, uint32_t& r1,
                                       uint32_t& r2, uint32_t& r3, uint32_t addr) {
    asm volatile("ldmatrix.sync.aligned.m8n8.x4.shared.b16 {%0,%1,%2,%3}, [%4];"
                 : "=r"(r0), "=r"(r1), "=r"(r2), "=r"(r3) : "r"(addr));
}
__device__ __forceinline__ void mma_16816(float& d0, float& d1, float& d2, float& d3,
                                          uint32_t a0, uint32_t a1, uint32_t a2, uint32_t a3,
                                          uint32_t b0, uint32_t b1) {
    asm volatile(
        "mma.sync.aligned.m16n8k16.row.col.f32.bf16.bf16.f32 "
        "{%0,%1,%2,%3},{%4,%5,%6,%7},{%8,%9},{%0,%1,%2,%3};"
        : "+f"(d0), "+f"(d1), "+f"(d2), "+f"(d3)
        : "r"(a0), "r"(a1), "r"(a2), "r"(a3), "r"(b0), "r"(b1));
}
__device__ __forceinline__ uint32_t pack_bf16x2(float lo_elem, float hi_elem) {
    uint32_t r;
    asm("cvt.rn.bf16x2.f32 %0, %1, %2;" : "=r"(r) : "f"(hi_elem), "f"(lo_elem));
    return r;
}
__device__ __forceinline__ float2 fadd2(float2 a, float2 b) {
    float2 d;
    asm("add.rn.f32x2 %0, %1, %2;"
        : "=l"(reinterpret_cast<unsigned long long&>(d))
        : "l"(reinterpret_cast<unsigned long long&>(a)),
          "l"(reinterpret_cast<unsigned long long&>(b)));
    return d;
}

// ---------------------------------------------------------------------------
// Kernel B (mma.sync, K=16, kA fused): CTA = (i-block of 128, b, j-16th).
// 256 thr / 8 warps.
//   Prologue: C[j][h] = mb1[h] + sum_{t,k<4} x[b,j,t,k]*mW1[5t+k,h]  (smem)
//   Mainloop per j: P[h,i] = W_hi[h,16k] @ E_hi[16k,i]; D init = C (fp32);
//                   acc += relu(D)  (f32x2-packed over i)
// Warp w owns h-tile [16w,16w+16); 16 n8 i-tiles; one mma per tile;
// paired B-ldsm. Epilogue: 2 transpose regions, 4 rounds.
// ---------------------------------------------------------------------------
__global__ __launch_bounds__(256, 2) void kB(const float* __restrict__ x,
                                             const float* __restrict__ mW1,
                                             const float* __restrict__ mb1) {
    __shared__ __align__(16) unsigned char s_all[34944];
    // carve: W 0..6144 | E0 6144..12288 | E1 12288..18432 | C 18432..34816
    unsigned char* s_w = s_all;
    unsigned char* s_e[2] = {s_all + 6144, s_all + 12288};
    float* s_cAll = reinterpret_cast<float*>(s_all + 18432);     // [32][128]
    float* s_base = reinterpret_cast<float*>(s_all + 12288);     // [32][40] overlay on E1

    const int tid  = threadIdx.x;
    const int lane = tid & 31, wid = tid >> 5;
    const int i0   = blockIdx.x * NI;        // 0,128,256,384
    const int b    = blockIdx.y;             // 0..3
    const int js   = blockIdx.z;             // 0..15
    const int jbase = js * JCHUNK;

    const int row  = tid >> 1;               // staged i-row (0..127)
    const int half = tid & 1;                // which 8-k half this thread stores
    const long estr = (long)T_ * F_;

    // ---- phase 1: stage W tile + base features ----
    if (tid < HID) {
        float wv[10];
#pragma unroll
        for (int t = 0; t < T_; ++t) wv[t] = mW1[(5 * t + 4) * HID + tid];
        uint4* dst = reinterpret_cast<uint4*>(s_w + tid * ROWB);
        dst[0] = make_uint4(pack_bf16x2(wv[0], wv[1]), pack_bf16x2(wv[2], wv[3]),
                            pack_bf16x2(wv[4], wv[5]), pack_bf16x2(wv[6], wv[7]));
        dst[1] = make_uint4(pack_bf16x2(wv[8], wv[9]), 0u, 0u, 0u);
    }
    for (int idx = tid; idx < JCHUNK * 40; idx += 256) {
        const int j = idx / 40, r = idx % 40;
        s_base[j * 40 + r] =
            x[((long)(b * N_ + jbase + j) * T_ + (r >> 2)) * F_ + (r & 3)];
    }
    __syncthreads();

    // ---- phase 2: compute C slice (fused kA) + stage E(j0) ----
    {
        const int h  = tid & 127;
        const int jh = tid >> 7;             // j-half: 0 -> j 0..15, 1 -> 16..31
        float w[40];
#pragma unroll
        for (int r = 0; r < 40; ++r)
            w[r] = mW1[(5 * (r >> 2) + (r & 3)) * HID + h];
        const float bias = mb1[h];
#pragma unroll 1
        for (int j = jh * 16; j < jh * 16 + 16; ++j) {
            float a = bias;
#pragma unroll
            for (int r = 0; r < 40; ++r) a = fmaf(s_base[j * 40 + r], w[r], a);
            s_cAll[j * HID + h] = a;
        }
    }
    const float* eg = x + ((long)(b * N_ + jbase) * T_) * F_ + 4 + i0 + row;
    {
        float v[10];
#pragma unroll
        for (int t = 0; t < T_; ++t) v[t] = eg[t * F_];
        uint4* dst = reinterpret_cast<uint4*>(s_e[0] + row * ROWB + half * 16);
        if (half == 0)
            dst[0] = make_uint4(pack_bf16x2(v[0], v[1]), pack_bf16x2(v[2], v[3]),
                                pack_bf16x2(v[4], v[5]), pack_bf16x2(v[6], v[7]));
        else
            dst[0] = make_uint4(pack_bf16x2(v[8], v[9]), 0u, 0u, 0u);
    }
    __syncthreads();

    // ---- load stationary A fragment (m16 x k16) ----
    uint32_t a0, a1, a2, a3;
    {
        const uint32_t wbase = smem_u32(s_w);
        const uint32_t aoff = (uint32_t)((wid * 16 + ((lane >> 3) & 1) * 8 + (lane & 7)) * ROWB
                                         + (lane >> 4) * 16);
        ldm_x4(a0, a1, a2, a3, wbase + aoff);
    }

    // paired-B ldsm: tiles {n:k0-7, n:k8-15, n+1:k0-7, n+1:k8-15}
    const uint32_t eoff = (uint32_t)(((lane >> 4) * 8 + (lane & 7)) * ROWB
                                     + ((lane >> 3) & 1) * 16);
    const uint32_t ebase[2] = {smem_u32(s_e[0]) + eoff, smem_u32(s_e[1]) + eoff};

    const int cidxA = wid * 16 + (lane >> 2);      // C row for d0/d1
    float2 acc2[32];                               // [n-tile pair over i]
#pragma unroll
    for (int q = 0; q < 32; ++q) acc2[q] = make_float2(0.f, 0.f);

#pragma unroll 1
    for (int jj = 0; jj < JCHUNK; ++jj) {
        const int buf = jj & 1;

        // prefetch next j's e into registers
        float vP[10];
        if (jj + 1 < JCHUNK) {
            const float* ep = eg + (long)(jj + 1) * estr;
#pragma unroll
            for (int t = 0; t < T_; ++t) vP[t] = ep[t * F_];
        }

        // ---- compute j from buf ----
        {
            const float cA = s_cAll[jj * HID + cidxA];
            const float cB = s_cAll[jj * HID + cidxA + 8];
            const uint32_t eb = ebase[buf];
#pragma unroll
            for (int n = 0; n < 16; n += 2) {
                uint32_t b0, b1, b2, b3;
                ldm_x4(b0, b1, b2, b3, eb + n * (8 * ROWB));
                float d0 = cA, d1 = cA, d2 = cB, d3 = cB;
                mma_16816(d0, d1, d2, d3, a0, a1, a2, a3, b0, b1);
                float e0 = cA, e1 = cA, e2 = cB, e3 = cB;
                mma_16816(e0, e1, e2, e3, a0, a1, a2, a3, b2, b3);
                acc2[n * 2 + 0] = fadd2(acc2[n * 2 + 0],
                                        make_float2(fmaxf(d0, 0.f), fmaxf(d1, 0.f)));
                acc2[n * 2 + 1] = fadd2(acc2[n * 2 + 1],
                                        make_float2(fmaxf(d2, 0.f), fmaxf(d3, 0.f)));
                acc2[n * 2 + 2] = fadd2(acc2[n * 2 + 2],
                                        make_float2(fmaxf(e0, 0.f), fmaxf(e1, 0.f)));
                acc2[n * 2 + 3] = fadd2(acc2[n * 2 + 3],
                                        make_float2(fmaxf(e2, 0.f), fmaxf(e3, 0.f)));
            }
        }

        // ---- stage next j into other buffer ----
        if (jj + 1 < JCHUNK) {
            uint4* dst = reinterpret_cast<uint4*>(s_e[buf ^ 1] + row * ROWB + half * 16);
            if (half == 0)
                dst[0] = make_uint4(pack_bf16x2(vP[0], vP[1]), pack_bf16x2(vP[2], vP[3]),
                                    pack_bf16x2(vP[4], vP[5]), pack_bf16x2(vP[6], vP[7]));
            else
                dst[0] = make_uint4(pack_bf16x2(vP[8], vP[9]), 0u, 0u, 0u);
        }
        __syncthreads();
    }

    // ---- epilogue: 2 parallel transpose regions, 4 rounds ----
    // acc2 mapping: tile n, part p (0..3): value = (p&1 ? .y : .x) of acc2[n*2 + (p>>1)]
    //   iL = n*8 + (lane&3)*2 + (p&1),  hL = (lane>>2) + ((p>>1)<<3)
    float* s_tr[2] = {reinterpret_cast<float*>(s_all),
                      reinterpret_cast<float*>(s_all + 8192)};   // 2 x 128i x 16h
    for (int rr = 0; rr < 4; ++rr) {
        const int wsel = wid & 3;          // writer group: wid = rr or rr+4
        if (wsel == rr) {
            float* tr = s_tr[wid >> 2];
#pragma unroll
            for (int n = 0; n < 16; ++n) {
#pragma unroll
                for (int p = 0; p < 4; ++p) {
                    const float vv = (p & 1) ? acc2[n * 2 + (p >> 1)].y
                                             : acc2[n * 2 + (p >> 1)].x;
                    const int iL = n * 8 + (lane & 3) * 2 + (p & 1);
                    const int hL = (lane >> 2) + ((p >> 1) << 3);
                    tr[iL * 16 + hL] = vv;
                }
            }
        }
        __syncthreads();
        {
            const int g   = tid >> 7;        // region 0/1 -> source warp rr + g*4
            const int iL  = tid & 127;
            const float4* src = reinterpret_cast<const float4*>(s_tr[g] + iL * 16);
            float* dst = g_part + ((long)(js * B_ + b) * N_ + i0 + iL) * HID
                       + (rr + g * 4) * 16;
            reinterpret_cast<float4*>(dst)[0] = src[0];
            reinterpret_cast<float4*>(dst)[1] = src[1];
            reinterpret_cast<float4*>(dst)[2] = src[2];
            reinterpret_cast<float4*>(dst)[3] = src[3];
        }
        __syncthreads();
    }
}

// ---------------------------------------------------------------------------
// Kernel C: per node — reduce 16 partial slices, apply mW2 (+ N*mb2),
// concat node_feat, 36 -> 128 (relu) -> 4 MLP. Block = 16 nodes, weights smem.
// ---------------------------------------------------------------------------
#define NPB 16
__global__ __launch_bounds__(128) void kC(const float* __restrict__ x,
                                          const float* __restrict__ mW2,
                                          const float* __restrict__ mb2,
                                          const float* __restrict__ iW1,
                                          const float* __restrict__ ib1,
                                          const float* __restrict__ iW2,
                                          const float* __restrict__ ib2,
                                          float* __restrict__ out) {
    const int tid = threadIdx.x;

    __shared__ float s_mW2[HID * MSGD];
    __shared__ float s_iW1[(MSGD + 4) * UPDH];
    __shared__ float s_iW2[UPDH * OUTD];
    __shared__ float s_mb2[MSGD], s_ib1[UPDH], s_ib2[OUTD];
    __shared__ float s_h[HID];
    __shared__ float s_red[4][MSGD];
    __shared__ float s_mi[MSGD + 4];
    __shared__ float s_h2[UPDH];
    __shared__ float s_nf[NPB][4];

    for (int i = tid; i < HID * MSGD; i += 128)        s_mW2[i] = mW2[i];
    for (int i = tid; i < (MSGD + 4) * UPDH; i += 128) s_iW1[i] = iW1[i];
    for (int i = tid; i < UPDH * OUTD; i += 128)       s_iW2[i] = iW2[i];
    if (tid < MSGD) s_mb2[tid] = mb2[tid];
    s_ib1[tid] = ib1[tid];
    if (tid < OUTD) s_ib2[tid] = ib2[tid];
    if (tid < NPB * 4) {
        const int nn = tid >> 2, k = tid & 3;
        s_nf[nn][k] = x[((long)(blockIdx.x * NPB + nn) * T_ + (T_ - 1)) * F_ + k];
    }
    __syncthreads();

    for (int nn = 0; nn < NPB; ++nn) {
        const long node = (long)blockIdx.x * NPB + nn;

        float h = 0.f;
#pragma unroll
        for (int p = 0; p < NSLICE; ++p)
            h += g_part[(long)p * (B_ * N_ * HID) + node * HID + tid];
        s_h[tid] = h;
        __syncthreads();

        {   // mW2 GEMV split 4 ways over k
            const int m = tid & 31, seg = tid >> 5;
            float a = 0.f;
#pragma unroll
            for (int k2 = 0; k2 < 32; ++k2) {
                const int k = seg * 32 + k2;
                a = fmaf(s_h[k], s_mW2[k * MSGD + m], a);
            }
            s_red[seg][m] = a;
        }
        __syncthreads();
        if (tid < MSGD)
            s_mi[tid] = s_red[0][tid] + s_red[1][tid] + s_red[2][tid] + s_red[3][tid]
                      + (float)N_ * s_mb2[tid];
        if (tid < 4) s_mi[MSGD + tid] = s_nf[nn][tid];
        __syncthreads();

        {   // 36 -> 128 relu
            float a = s_ib1[tid];
#pragma unroll
            for (int k = 0; k < MSGD + 4; ++k)
                a = fmaf(s_mi[k], s_iW1[k * UPDH + tid], a);
            s_h2[tid] = fmaxf(a, 0.f);
        }
        __syncthreads();

        {   // 128 -> 4: warp o computes output o, shuffle-reduce
            const int o = tid >> 5, lane = tid & 31;
            float a = 0.f;
#pragma unroll
            for (int kk = 0; kk < 4; ++kk) {
                const int k = lane + kk * 32;
                a = fmaf(s_h2[k], s_iW2[k * OUTD + o], a);
            }
#pragma unroll
            for (int off = 16; off; off >>= 1) a += __shfl_xor_sync(~0u, a, off);
            if (lane == 0) out[node * OUTD + o] = a + s_ib2[o];
        }
        __syncthreads();
    }
}

// ---------------------------------------------------------------------------
extern "C" void kernel_launch(void* const* d_in, const int* in_sizes, int n_in,
                              void* d_out, int out_size) {
    const float* x   = (const float*)d_in[0];
    const float* mW1 = (const float*)d_in[1];
    const float* mb1 = (const float*)d_in[2];
    const float* mW2 = (const float*)d_in[3];
    const float* mb2 = (const float*)d_in[4];
    const float* iW1 = (const float*)d_in[5];
    const float* ib1 = (const float*)d_in[6];
    const float* iW2 = (const float*)d_in[7];
    const float* ib2 = (const float*)d_in[8];
    float* out = (float*)d_out;

    dim3 gB(N_ / NI, B_, JSPLIT);                     // (4, 4, 16) = 256 CTAs
    kB<<<gB, 256>>>(x, mW1, mb1);

    kC<<<B_ * N_ / NPB, HID>>>(x, mW2, mb2, iW1, ib1, iW2, ib2, out);
}